// round 3
// baseline (speedup 1.0000x reference)
#include <cuda_runtime.h>

// GraphNorm: x (131072, 256) fp32, 64 graphs x 2048 rows x 256 units.
// out = gamma * (x - mean_g,u) / (std_g,u + 1e-5) + beta.
//
// Three-kernel barrier-light pipeline:
//   k1: partial sum/sumsq per (slice, graph, unit) -> __device__ scratch
//       (x read with L2::evict_last so it stays resident for k3)
//   k2: finalize mean / inv(std+eps) per (graph, unit)
//   k3: pure streaming normalize (no __syncthreads in hot path),
//       x re-read evict_first (L2 hit), gamma/beta evict_first, st.cs out.

#define UNITS   256
#define BATCH   64
#define NPG     2048
#define UB      32          // units per block (x-dim chunk)
#define VEC     8
#define EPS     1e-5f

#define S1      4           // row slices in stats kernel  (512 rows each)
#define S3      8           // row slices in norm kernel   (256 rows each)
#define T256    256

__device__ float g_psum[S1][BATCH][UNITS];
__device__ float g_psq [S1][BATCH][UNITS];
__device__ float g_mean[BATCH][UNITS];
__device__ float g_inv [BATCH][UNITS];

__device__ __forceinline__ void ld_v8_evict_last(const float* p, float* r) {
    asm volatile("ld.global.L2::evict_last.v8.b32 {%0,%1,%2,%3,%4,%5,%6,%7}, [%8];"
                 : "=f"(r[0]), "=f"(r[1]), "=f"(r[2]), "=f"(r[3]),
                   "=f"(r[4]), "=f"(r[5]), "=f"(r[6]), "=f"(r[7])
                 : "l"(p));
}
__device__ __forceinline__ void ld_v8_evict_first(const float* p, float* r) {
    asm volatile("ld.global.L2::evict_first.v8.b32 {%0,%1,%2,%3,%4,%5,%6,%7}, [%8];"
                 : "=f"(r[0]), "=f"(r[1]), "=f"(r[2]), "=f"(r[3]),
                   "=f"(r[4]), "=f"(r[5]), "=f"(r[6]), "=f"(r[7])
                 : "l"(p));
}
__device__ __forceinline__ void st_v4_cs(float* p, float a, float b, float c, float d) {
    asm volatile("st.global.cs.v4.f32 [%0], {%1,%2,%3,%4};"
                 :: "l"(p), "f"(a), "f"(b), "f"(c), "f"(d));
}

// ---------------- k1: partial stats ----------------
// grid (8, 64, 4), 256 threads (8 warps).
// Block covers rows [slice*512, +512) x units [uc*32, +32).
__global__ void __launch_bounds__(T256)
k1_partial_stats(const float* __restrict__ x)
{
    const int uc    = blockIdx.x;
    const int g     = blockIdx.y;
    const int slice = blockIdx.z;
    const int lane  = threadIdx.x & 31;
    const int w     = threadIdx.x >> 5;        // 0..7
    const int ug    = lane & 3;                // 8 units each
    const int rg    = lane >> 2;               // 0..7

    const size_t ubase = (size_t)uc * UB + (size_t)ug * VEC;
    const size_t gbase = (size_t)g * NPG * UNITS;
    const int row0 = slice * 512 + w * 8 + rg;

    float sum[VEC], sq[VEC];
    #pragma unroll
    for (int j = 0; j < VEC; ++j) { sum[j] = 0.f; sq[j] = 0.f; }

    #pragma unroll
    for (int i = 0; i < 8; ++i) {              // 8 iters * 64 rows = 512 rows
        const int row = row0 + i * 64;
        float v[VEC];
        ld_v8_evict_last(x + gbase + (size_t)row * UNITS + ubase, v);
        #pragma unroll
        for (int j = 0; j < VEC; ++j) {
            sum[j] += v[j];
            sq[j] = fmaf(v[j], v[j], sq[j]);
        }
    }

    // reduce over the 8 row-subgroups within the warp (lane bits 2..4)
    #pragma unroll
    for (int m = 4; m <= 16; m <<= 1) {
        #pragma unroll
        for (int j = 0; j < VEC; ++j) {
            sum[j] += __shfl_xor_sync(0xffffffffu, sum[j], m);
            sq[j]  += __shfl_xor_sync(0xffffffffu, sq[j],  m);
        }
    }

    __shared__ float s_sum[8][UB];
    __shared__ float s_sq [8][UB];
    if (lane < 4) {
        #pragma unroll
        for (int j = 0; j < VEC; ++j) {
            s_sum[w][ug * VEC + j] = sum[j];
            s_sq [w][ug * VEC + j] = sq[j];
        }
    }
    __syncthreads();

    if (w == 0) {                               // 32 lanes <-> 32 units
        float a = 0.f, b = 0.f;
        #pragma unroll
        for (int k = 0; k < 8; ++k) {
            a += s_sum[k][lane];
            b += s_sq [k][lane];
        }
        const int u = uc * UB + lane;
        g_psum[slice][g][u] = a;
        g_psq [slice][g][u] = b;
    }
}

// ---------------- k2: finalize mean / inv ----------------
// grid 64 (graphs), 256 threads (units).
__global__ void __launch_bounds__(T256)
k2_finalize()
{
    const int g = blockIdx.x;
    const int u = threadIdx.x;
    float s = 0.f, q = 0.f;
    #pragma unroll
    for (int k = 0; k < S1; ++k) {
        s += g_psum[k][g][u];
        q += g_psq [k][g][u];
    }
    const float invn = 1.0f / (float)NPG;
    const float mean = s * invn;
    float var = fmaf(-mean, mean, q * invn);
    var = fmaxf(var, 0.0f);
    g_mean[g][u] = mean;
    g_inv [g][u] = 1.0f / (sqrtf(var) + EPS);
}

// ---------------- k3: streaming normalize ----------------
// grid (8, 64, 8), 256 threads. Block: rows [z*256, +256) x units [uc*32, +32).
// No __syncthreads; each thread loads its own 8 mean/inv values.
__global__ void __launch_bounds__(T256)
k3_normalize(const float* __restrict__ x,
             const float* __restrict__ gamma,
             const float* __restrict__ beta,
             float* __restrict__ out)
{
    const int uc    = blockIdx.x;
    const int g     = blockIdx.y;
    const int slice = blockIdx.z;
    const int lane  = threadIdx.x & 31;
    const int w     = threadIdx.x >> 5;
    const int ug    = lane & 3;
    const int rg    = lane >> 2;

    const size_t ubase = (size_t)uc * UB + (size_t)ug * VEC;
    const size_t gbase = (size_t)g * NPG * UNITS;
    const int row0 = slice * 256 + w * 8 + rg;

    float mean[VEC], inv[VEC];
    ld_v8_evict_last(&g_mean[g][0] + ubase, mean);   // tiny, keep hot
    ld_v8_evict_last(&g_inv [g][0] + ubase, inv);

    #pragma unroll
    for (int i = 0; i < 4; ++i) {              // 4 iters * 64 rows = 256 rows
        const int row = row0 + i * 64;
        const size_t idx = gbase + (size_t)row * UNITS + ubase;
        float v[VEC], ga[VEC], be[VEC];
        ld_v8_evict_first(x     + idx, v);     // 2nd read: L2 hit, then drop
        ld_v8_evict_first(gamma + idx, ga);
        ld_v8_evict_first(beta  + idx, be);
        float o[VEC];
        #pragma unroll
        for (int j = 0; j < VEC; ++j)
            o[j] = fmaf((v[j] - mean[j]) * inv[j], ga[j], be[j]);
        st_v4_cs(out + idx,     o[0], o[1], o[2], o[3]);
        st_v4_cs(out + idx + 4, o[4], o[5], o[6], o[7]);
    }
}

extern "C" void kernel_launch(void* const* d_in, const int* in_sizes, int n_in,
                              void* d_out, int out_size) {
    const float* x     = (const float*)d_in[0];
    const float* gamma = (const float*)d_in[1];
    const float* beta  = (const float*)d_in[2];
    float* out = (float*)d_out;

    dim3 g1(UNITS / UB, BATCH, S1);   // (8, 64, 4)
    k1_partial_stats<<<g1, T256>>>(x);
    k2_finalize<<<BATCH, T256>>>();
    dim3 g3(UNITS / UB, BATCH, S3);   // (8, 64, 8)
    k3_normalize<<<g3, T256>>>(x, gamma, beta, out);
}